// round 14
// baseline (speedup 1.0000x reference)
#include <cuda_runtime.h>
#include <math.h>

#define CUTOFF   1.5f
#define NMAX     16384
#define NCCAP    15
#define NCMAX    (NCCAP*NCCAP*NCCAP + 9)   // 3384
#define NCELLS   (NCCAP*NCCAP*NCCAP)       // 3375
#define CAP      24                         // max atoms per cell
#define MAXC     160                        // max flat candidates per cell
#define FBLK     128                        // force block threads (4 warps, 4 atoms)

// ---------------- device scratch (no allocations allowed) ----------------
__device__ float        g_cellm[9];          // cell matrix (rows = lattice vectors)
__device__ int          g_nc[3];
__device__ int          g_count[NCMAX];      // MUST be zero at kernel_launch entry
__device__ float4       g_cpos[NCMAX*CAP];   // padded per-cell atom lists (xyz + spec)
__device__ float4       g_apos[NMAX];        // per-atom: xyz, w = spec + 8*cid
__device__ float4       g_cand[NCELLS*MAXC]; // flat shifted candidate lists
__device__ int          g_ccount[NCELLS];    // candidates per cell
__device__ float4       g_tbl[64];           // (1/sig, eps/alp, alp-1, eps/sig)
__device__ float        g_sig2[64];          // sig^2
__device__ float        g_part[4096];        // per-block energy partials
__device__ unsigned int g_done = 0u;         // reset by last force block

// =======================================================================
// k_bin: tables + cell setup + bin atoms into padded cell lists.
// =======================================================================
__global__ void __launch_bounds__(128) k_bin(
    const float* __restrict__ pos, const float* __restrict__ cell,
    const float* __restrict__ sig, const float* __restrict__ eps,
    const float* __restrict__ alp, const int* __restrict__ spec,
    int n, int S)
{
    int i = blockIdx.x * blockDim.x + threadIdx.x;

    if (blockIdx.x == 0 && threadIdx.x < S*S) {
        int t = threadIdx.x;
        float sg = sig[t], ep = eps[t], al = alp[t];
        g_tbl[t]  = make_float4(1.0f/sg, ep/al, al - 1.0f, ep/sg);
        g_sig2[t] = sg * sg;
    }

    float c00=cell[0], c01=cell[1], c02=cell[2];
    float c10=cell[3], c11=cell[4], c12=cell[5];
    float c20=cell[6], c21=cell[7], c22=cell[8];
    float det = c00*(c11*c22 - c12*c21) - c01*(c10*c22 - c12*c20) + c02*(c10*c21 - c11*c20);
    float id = 1.0f / det;
    float i00=(c11*c22-c12*c21)*id, i01=(c02*c21-c01*c22)*id, i02=(c01*c12-c02*c11)*id;
    float i10=(c12*c20-c10*c22)*id, i11=(c00*c22-c02*c20)*id, i12=(c02*c10-c00*c12)*id;
    float i20=(c10*c21-c11*c20)*id, i21=(c01*c20-c00*c21)*id, i22=(c00*c11-c01*c10)*id;
    float w0 = rsqrtf(i00*i00 + i10*i10 + i20*i20);
    float w1 = rsqrtf(i01*i01 + i11*i11 + i21*i21);
    float w2 = rsqrtf(i02*i02 + i12*i12 + i22*i22);
    int n0 = (int)floorf(w0 / CUTOFF); n0 = n0 < 1 ? 1 : (n0 > NCCAP ? NCCAP : n0);
    int n1 = (int)floorf(w1 / CUTOFF); n1 = n1 < 1 ? 1 : (n1 > NCCAP ? NCCAP : n1);
    int n2 = (int)floorf(w2 / CUTOFF); n2 = n2 < 1 ? 1 : (n2 > NCCAP ? NCCAP : n2);

    if (i == 0) {
        g_cellm[0]=c00; g_cellm[1]=c01; g_cellm[2]=c02;
        g_cellm[3]=c10; g_cellm[4]=c11; g_cellm[5]=c12;
        g_cellm[6]=c20; g_cellm[7]=c21; g_cellm[8]=c22;
        g_nc[0]=n0; g_nc[1]=n1; g_nc[2]=n2;
    }

    if (i < n) {
        float x = pos[3*i], y = pos[3*i+1], z = pos[3*i+2];
        float f0 = x*i00 + y*i10 + z*i20;
        float f1 = x*i01 + y*i11 + z*i21;
        float f2 = x*i02 + y*i12 + z*i22;
        f0 -= floorf(f0); f1 -= floorf(f1); f2 -= floorf(f2);
        int a = (int)(f0 * (float)n0); a = a >= n0 ? n0-1 : (a < 0 ? 0 : a);
        int b = (int)(f1 * (float)n1); b = b >= n1 ? n1-1 : (b < 0 ? 0 : b);
        int c = (int)(f2 * (float)n2); c = c >= n2 ? n2-1 : (c < 0 ? 0 : c);
        int cid = (c*n1 + b)*n0 + a;
        int sp = spec[i];
        g_apos[i] = make_float4(x, y, z, (float)(sp + 8*cid));
        int r = atomicAdd(&g_count[cid], 1);
        if (r < CAP)
            g_cpos[cid*CAP + r] = make_float4(x, y, z, (float)sp);
    }
}

// =======================================================================
// k_build: ONE WARP PER CELL. Gathers the cell's 27-neighborhood once,
// applies PBC shifts, and writes a compact flat candidate list. Pure
// streaming (no __syncthreads, no compute phase behind it).
// =======================================================================
__global__ void __launch_bounds__(256) k_build()
{
    int warp = (blockIdx.x * 256 + threadIdx.x) >> 5;
    int lane = threadIdx.x & 31;
    int ncx = g_nc[0], ncy = g_nc[1], ncz = g_nc[2];
    int nctot = ncx*ncy*ncz;
    int cid = warp;
    if (cid >= nctot) return;

    int cnt = 0, cbase = 0;
    float shx = 0.f, shy = 0.f, shz = 0.f;
    if (lane < 27) {
        int cx = cid % ncx, cy = (cid / ncx) % ncy, cz = cid / (ncx*ncy);
        int ox = lane % 3 - 1, oy = (lane / 3) % 3 - 1, oz = lane / 9 - 1;
        int rx = cx + ox, ry = cy + oy, rz = cz + oz;
        int wx = 0, wy = 0, wz = 0;
        if (rx < 0) { rx += ncx; wx = -1; } else if (rx >= ncx) { rx -= ncx; wx = 1; }
        if (ry < 0) { ry += ncy; wy = -1; } else if (ry >= ncy) { ry -= ncy; wy = 1; }
        if (rz < 0) { rz += ncz; wz = -1; } else if (rz >= ncz) { rz -= ncz; wz = 1; }
        shx = wx*g_cellm[0] + wy*g_cellm[3] + wz*g_cellm[6];
        shy = wx*g_cellm[1] + wy*g_cellm[4] + wz*g_cellm[7];
        shz = wx*g_cellm[2] + wy*g_cellm[5] + wz*g_cellm[8];
        int cidn = (rz*ncy + ry)*ncx + rx;
        cnt = g_count[cidn];
        cnt = cnt > CAP ? CAP : cnt;
        cbase = cidn * CAP;
    }
    // warp exclusive scan of cnt
    int inc = cnt;
    #pragma unroll
    for (int o = 1; o < 32; o <<= 1) {
        int x = __shfl_up_sync(0xffffffffu, inc, o);
        if (lane >= o) inc += x;
    }
    int ntot = __shfl_sync(0xffffffffu, inc, 26);
    int off  = inc - cnt;
    if (lane == 0) g_ccount[cid] = ntot > MAXC ? MAXC : ntot;

    int base = cid * MAXC;
    for (int m = 0; m < cnt; m++) {
        int q = off + m;
        if (q < MAXC) {
            float4 p = g_cpos[cbase + m];
            g_cand[base + q] = make_float4(p.x + shx, p.y + shy, p.z + shz, p.w);
        }
    }
}

// =======================================================================
// k_force: ONE WARP PER ATOM. Preamble = 1 apos load + 1 count load.
// Inner loop: coalesced stride-32 sweep of the dense candidate list,
// warp-uniform extent, no collectives, single rare-hit branch.
// =======================================================================
__global__ void __launch_bounds__(FBLK) k_force(
    float* __restrict__ out, int n, int S)
{
    __shared__ float4 s_tbl[64];
    __shared__ float  s_sig2[64];
    __shared__ float4 s_f[FBLK/32];
    __shared__ int    s_flag;

    int t = threadIdx.x, lane = t & 31, warp = t >> 5;
    if (t < S*S) { s_tbl[t] = g_tbl[t]; s_sig2[t] = g_sig2[t]; }
    __syncthreads();

    int a = blockIdx.x * (FBLK/32) + warp;
    float fx = 0.f, fy = 0.f, fz = 0.f, en = 0.f;

    if (a < n) {
        float4 pa = __ldg(&g_apos[a]);
        int w   = (int)pa.w;
        int si  = w & 7;
        int cid = w >> 3;
        int ntot = __ldg(&g_ccount[cid]);
        int base = cid * MAXC;
        int sBase = si * S;

        for (int q = lane; q < ntot; q += 32) {
            float4 cb = __ldg(&g_cand[base + q]);
            float dx = cb.x - pa.x;
            float dy = cb.y - pa.y;
            float dz = cb.z - pa.z;
            float r2 = fmaf(dx,dx, fmaf(dy,dy, dz*dz));
            int idx = sBase + (int)cb.w;
            // r2 < sig^2  <=>  1 - r/sig > 0  (implies r < cutoff); r2>eps skips self
            if (r2 < s_sig2[idx] && r2 > 1e-12f) {
                float rinv = rsqrtf(r2);
                float r = r2 * rinv;
                float4 tb = s_tbl[idx];
                float f = fmaf(-r, tb.x, 1.0f);          // 1 - r/sig
                float pw = __powf(f, tb.z);              // f^(alpha-1)
                en = fmaf(tb.y * f, pw, en);             // eps/alpha * f^alpha
                float coef = tb.w * pw * rinv;           // eps/sig * f^(a-1) / r
                fx = fmaf(-coef, dx, fx);
                fy = fmaf(-coef, dy, fy);
                fz = fmaf(-coef, dz, fz);
            }
        }
    }

    // warp reduction
    #pragma unroll
    for (int off = 16; off; off >>= 1) {
        fx += __shfl_down_sync(0xffffffffu, fx, off);
        fy += __shfl_down_sync(0xffffffffu, fy, off);
        fz += __shfl_down_sync(0xffffffffu, fz, off);
        en += __shfl_down_sync(0xffffffffu, en, off);
    }
    if (lane == 0) {
        if (a < n) {
            out[1 + 3*a + 0] = fx;
            out[1 + 3*a + 1] = fy;
            out[1 + 3*a + 2] = fz;
        }
        s_f[warp] = make_float4(0.f, 0.f, 0.f, (a < n) ? en : 0.f);
    }
    __syncthreads();

    if (t == 0) {
        float e = 0.f;
        #pragma unroll
        for (int w = 0; w < FBLK/32; w++) e += s_f[w].w;
        g_part[blockIdx.x] = e;
        __threadfence();
        unsigned int d = atomicAdd(&g_done, 1u);
        s_flag = (d == gridDim.x - 1) ? 1 : 0;
    }
    __syncthreads();

    // last block: reduce partials, write energy, reset scratch state
    if (s_flag) {
        __threadfence();
        __shared__ float s_red[FBLK];
        int nb = gridDim.x;
        float acc = 0.f;
        for (int k = t; k < nb; k += FBLK) acc += g_part[k];
        s_red[t] = acc;
        __syncthreads();
        for (int o = FBLK/2; o > 0; o >>= 1) {
            if (t < o) s_red[t] += s_red[t + o];
            __syncthreads();
        }
        if (t == 0) {
            out[0] = 0.5f * s_red[0];
            g_done = 0u;
        }
        for (int k = t; k < NCMAX; k += FBLK) g_count[k] = 0;
    }
}

// ---------------- launch ----------------
extern "C" void kernel_launch(void* const* d_in, const int* in_sizes, int n_in,
                              void* d_out, int out_size) {
    const float* pos  = (const float*)d_in[0];
    const float* cell = (const float*)d_in[1];
    const float* sig  = (const float*)d_in[2];
    const float* eps  = (const float*)d_in[3];
    const float* alp  = (const float*)d_in[4];
    const int*   spec = (const int*)  d_in[5];
    int n  = in_sizes[5];
    int ss = in_sizes[2];
    int S = 1; while (S*S < ss) S++;
    float* out = (float*)d_out;

    k_bin<<<(n + 127)/128, 128>>>(pos, cell, sig, eps, alp, spec, n, S);
    k_build<<<(NCELLS*32 + 255)/256, 256>>>();
    k_force<<<(n + FBLK/32 - 1)/(FBLK/32), FBLK>>>(out, n, S);
}

// round 15
// speedup vs baseline: 1.1307x; 1.1307x over previous
#include <cuda_runtime.h>
#include <math.h>

#define CUTOFF   1.5f
#define NMAX     16384
#define NCCAP    15
#define NCELLS   (NCCAP*NCCAP*NCCAP)       // 3375
#define MAXC     160                        // flat candidates per cell
#define FBLK     128                        // force block threads (4 warps)

// ---------------- device scratch (no allocations allowed) ----------------
__device__ float4       g_apos[NMAX];        // per-atom: xyz, w = spec + 8*cid
__device__ float4       g_cand[NCELLS*MAXC]; // flat shifted candidate lists
__device__ int          g_ccnt[NCELLS];      // MUST be zero at entry (reset by force)
__device__ float4       g_tbl[64];           // (1/sig, eps/alp, alp-1, eps/sig)
__device__ float        g_sig2[64];          // sig^2
__device__ float        g_part[4096];        // per-block energy partials
__device__ unsigned int g_done = 0u;         // reset by last force block

// =======================================================================
// k_scat: ONE WARP PER ATOM. Lanes 0..26 scatter the atom (with the
// correct periodic shift) into each of its 27 home-cell candidate lists.
// Inverse of the validated k_build wrap: home c_raw = ca + d;
//   c_raw < 0  -> wrap up,  shift +L (atom appears beyond far edge)
//   c_raw >= n -> wrap down, shift -L
// =======================================================================
__global__ void __launch_bounds__(128) k_scat(
    const float* __restrict__ pos, const float* __restrict__ cell,
    const float* __restrict__ sig, const float* __restrict__ eps,
    const float* __restrict__ alp, const int* __restrict__ spec,
    int n, int S)
{
    int t = threadIdx.x, lane = t & 31, warp = t >> 5;

    // species tables (block 0 only)
    if (blockIdx.x == 0 && t < S*S) {
        float sg = sig[t], ep = eps[t], al = alp[t];
        g_tbl[t]  = make_float4(1.0f/sg, ep/al, al - 1.0f, ep/sg);
        g_sig2[t] = sg * sg;
    }

    int a = blockIdx.x * 4 + warp;
    if (a >= n) return;

    // cell matrix + inverse (registers, all lanes redundantly)
    float c00=cell[0], c01=cell[1], c02=cell[2];
    float c10=cell[3], c11=cell[4], c12=cell[5];
    float c20=cell[6], c21=cell[7], c22=cell[8];
    float det = c00*(c11*c22 - c12*c21) - c01*(c10*c22 - c12*c20) + c02*(c10*c21 - c11*c20);
    float id = 1.0f / det;
    float i00=(c11*c22-c12*c21)*id, i01=(c02*c21-c01*c22)*id, i02=(c01*c12-c02*c11)*id;
    float i10=(c12*c20-c10*c22)*id, i11=(c00*c22-c02*c20)*id, i12=(c02*c10-c00*c12)*id;
    float i20=(c10*c21-c11*c20)*id, i21=(c01*c20-c00*c21)*id, i22=(c00*c11-c01*c10)*id;
    float w0 = rsqrtf(i00*i00 + i10*i10 + i20*i20);
    float w1 = rsqrtf(i01*i01 + i11*i11 + i21*i21);
    float w2 = rsqrtf(i02*i02 + i12*i12 + i22*i22);
    int n0 = (int)floorf(w0 / CUTOFF); n0 = n0 < 1 ? 1 : (n0 > NCCAP ? NCCAP : n0);
    int n1 = (int)floorf(w1 / CUTOFF); n1 = n1 < 1 ? 1 : (n1 > NCCAP ? NCCAP : n1);
    int n2 = (int)floorf(w2 / CUTOFF); n2 = n2 < 1 ? 1 : (n2 > NCCAP ? NCCAP : n2);

    float x = pos[3*a], y = pos[3*a+1], z = pos[3*a+2];
    float f0 = x*i00 + y*i10 + z*i20;
    float f1 = x*i01 + y*i11 + z*i21;
    float f2 = x*i02 + y*i12 + z*i22;
    f0 -= floorf(f0); f1 -= floorf(f1); f2 -= floorf(f2);
    int ax = (int)(f0 * (float)n0); ax = ax >= n0 ? n0-1 : (ax < 0 ? 0 : ax);
    int ay = (int)(f1 * (float)n1); ay = ay >= n1 ? n1-1 : (ay < 0 ? 0 : ay);
    int az = (int)(f2 * (float)n2); az = az >= n2 ? n2-1 : (az < 0 ? 0 : az);
    int cid = (az*n1 + ay)*n0 + ax;
    int sp = spec[a];

    if (lane == 13)   // center offset (0,0,0): also record per-atom data
        g_apos[a] = make_float4(x, y, z, (float)(sp + 8*cid));

    if (lane < 27) {
        int dx = lane % 3 - 1, dy = (lane / 3) % 3 - 1, dz = lane / 9 - 1;
        int cx = ax + dx, wx = 0;
        int cy = ay + dy, wy = 0;
        int cz = az + dz, wz = 0;
        if (cx < 0) { cx += n0; wx = 1; } else if (cx >= n0) { cx -= n0; wx = -1; }
        if (cy < 0) { cy += n1; wy = 1; } else if (cy >= n1) { cy -= n1; wy = -1; }
        if (cz < 0) { cz += n2; wz = 1; } else if (cz >= n2) { cz -= n2; wz = -1; }
        int ct = (cz*n1 + cy)*n0 + cx;
        float shx = wx*c00 + wy*c10 + wz*c20;
        float shy = wx*c01 + wy*c11 + wz*c21;
        float shz = wx*c02 + wy*c12 + wz*c22;
        int slot = atomicAdd(&g_ccnt[ct], 1);
        if (slot < MAXC)
            g_cand[ct*MAXC + slot] = make_float4(x + shx, y + shy, z + shz, (float)sp);
    }
}

// =======================================================================
// k_force: ONE WARP PER ATOM. Preamble = 1 apos load + 1 count load.
// Inner loop: coalesced stride-32 sweep of the dense candidate list,
// warp-uniform extent, no collectives, single rare-hit branch.
// =======================================================================
__global__ void __launch_bounds__(FBLK) k_force(
    float* __restrict__ out, int n, int S)
{
    __shared__ float4 s_tbl[64];
    __shared__ float  s_sig2[64];
    __shared__ float4 s_f[FBLK/32];
    __shared__ int    s_flag;

    int t = threadIdx.x, lane = t & 31, warp = t >> 5;
    if (t < S*S) { s_tbl[t] = g_tbl[t]; s_sig2[t] = g_sig2[t]; }
    __syncthreads();

    int a = blockIdx.x * (FBLK/32) + warp;
    float fx = 0.f, fy = 0.f, fz = 0.f, en = 0.f;

    if (a < n) {
        float4 pa = __ldg(&g_apos[a]);
        int w   = (int)pa.w;
        int si  = w & 7;
        int cid = w >> 3;
        int ntot = __ldg(&g_ccnt[cid]);
        ntot = ntot > MAXC ? MAXC : ntot;
        int base = cid * MAXC;
        int sBase = si * S;

        for (int q = lane; q < ntot; q += 32) {
            float4 cb = __ldg(&g_cand[base + q]);
            float dx = cb.x - pa.x;
            float dy = cb.y - pa.y;
            float dz = cb.z - pa.z;
            float r2 = fmaf(dx,dx, fmaf(dy,dy, dz*dz));
            int idx = sBase + (int)cb.w;
            // r2 < sig^2  <=>  1 - r/sig > 0  (implies r < cutoff); r2>eps skips self
            if (r2 < s_sig2[idx] && r2 > 1e-12f) {
                float rinv = rsqrtf(r2);
                float r = r2 * rinv;
                float4 tb = s_tbl[idx];
                float f = fmaf(-r, tb.x, 1.0f);          // 1 - r/sig
                float pw = __powf(f, tb.z);              // f^(alpha-1)
                en = fmaf(tb.y * f, pw, en);             // eps/alpha * f^alpha
                float coef = tb.w * pw * rinv;           // eps/sig * f^(a-1) / r
                fx = fmaf(-coef, dx, fx);
                fy = fmaf(-coef, dy, fy);
                fz = fmaf(-coef, dz, fz);
            }
        }
    }

    // warp reduction
    #pragma unroll
    for (int off = 16; off; off >>= 1) {
        fx += __shfl_down_sync(0xffffffffu, fx, off);
        fy += __shfl_down_sync(0xffffffffu, fy, off);
        fz += __shfl_down_sync(0xffffffffu, fz, off);
        en += __shfl_down_sync(0xffffffffu, en, off);
    }
    if (lane == 0) {
        if (a < n) {
            out[1 + 3*a + 0] = fx;
            out[1 + 3*a + 1] = fy;
            out[1 + 3*a + 2] = fz;
        }
        s_f[warp] = make_float4(0.f, 0.f, 0.f, (a < n) ? en : 0.f);
    }
    __syncthreads();

    if (t == 0) {
        float e = 0.f;
        #pragma unroll
        for (int w = 0; w < FBLK/32; w++) e += s_f[w].w;
        g_part[blockIdx.x] = e;
        __threadfence();
        unsigned int d = atomicAdd(&g_done, 1u);
        s_flag = (d == gridDim.x - 1) ? 1 : 0;
    }
    __syncthreads();

    // last block: reduce partials, write energy, reset scratch state
    if (s_flag) {
        __threadfence();
        __shared__ float s_red[FBLK];
        int nb = gridDim.x;
        float acc = 0.f;
        for (int k = t; k < nb; k += FBLK) acc += g_part[k];
        s_red[t] = acc;
        __syncthreads();
        for (int o = FBLK/2; o > 0; o >>= 1) {
            if (t < o) s_red[t] += s_red[t + o];
            __syncthreads();
        }
        if (t == 0) {
            out[0] = 0.5f * s_red[0];
            g_done = 0u;
        }
        for (int k = t; k < NCELLS; k += FBLK) g_ccnt[k] = 0;
    }
}

// ---------------- launch ----------------
extern "C" void kernel_launch(void* const* d_in, const int* in_sizes, int n_in,
                              void* d_out, int out_size) {
    const float* pos  = (const float*)d_in[0];
    const float* cell = (const float*)d_in[1];
    const float* sig  = (const float*)d_in[2];
    const float* eps  = (const float*)d_in[3];
    const float* alp  = (const float*)d_in[4];
    const int*   spec = (const int*)  d_in[5];
    int n  = in_sizes[5];
    int ss = in_sizes[2];
    int S = 1; while (S*S < ss) S++;
    float* out = (float*)d_out;

    k_scat<<<(n + 3)/4, 128>>>(pos, cell, sig, eps, alp, spec, n, S);
    k_force<<<(n + FBLK/32 - 1)/(FBLK/32), FBLK>>>(out, n, S);
}